// round 11
// baseline (speedup 1.0000x reference)
#include <cuda_runtime.h>
#include <cstdint>

#define N 160
#define NCELLS (N * N)
#define NDIAG (2 * N - 1)  // 319 anti-diagonals, 0-based s = ri + c
#define BC 512
#define CH 8
#define BATCH 64
#define BIGV 1e10f
#define GAMMA 0.01f
#define FULLM 0xffffffffu

// exp/log folding constants
#define KLOG2E 144.26950408889634f   // (1/GAMMA) * log2(e)
#define NEGK (-144.26950408889634f)
#define NGLN2 (-0.006931471805599453f)  // -GAMMA * ln(2)

// Softmin gradient weights per cell: (wd, wu) packed; wl = 1 - wd - wu.
// Diag-major compacted. +256 cells padding for fixed-size prefetch overrun.
__device__ float2 g_w2[(size_t)BC * NCELLS + 256];
__device__ float g_sdtw[BC];
__device__ float g_lt[BC];

__device__ __forceinline__ int doffs(int s) {
    return (s <= 160) ? (s * (s + 1)) / 2
                      : NCELLS - ((319 - s) * (320 - s)) / 2;
}

__device__ __forceinline__ float ex2f(float x) {
    float r;
    asm("ex2.approx.f32 %0, %1;" : "=f"(r) : "f"(x));
    return r;
}
__device__ __forceinline__ float lg2f(float x) {
    float r;
    asm("lg2.approx.f32 %0, %1;" : "=f"(r) : "f"(x));
    return r;
}
__device__ __forceinline__ float rcpf(float x) {
    float r;
    asm("rcp.approx.f32 %0, %1;" : "=f"(r) : "f"(x));
    return r;
}
__device__ __forceinline__ uint32_t smem_u32(const void* p) {
    return (uint32_t)__cvta_generic_to_shared(p);
}
__device__ __forceinline__ void cpa8(uint32_t dst, const void* src) {
    asm volatile("cp.async.ca.shared.global [%0], [%1], 8;" ::"r"(dst),
                 "l"(src));
}
#define CP_COMMIT() asm volatile("cp.async.commit_group;" ::: "memory")
#define CP_WAIT6() asm volatile("cp.async.wait_group 6;" ::: "memory")

__global__ __launch_bounds__(128) void dtw_warp_kernel(
    const float* __restrict__ input, const float* __restrict__ target) {
    const int lane = threadIdx.x & 31;
    const int w = threadIdx.x >> 5;
    const int prob = blockIdx.x * 4 + w;  // 1 warp = 1 problem

    __shared__ float sp_s[4][N];
    __shared__ float2 ring[4][8][N];  // per-warp 8-slot diagonal ring
    __shared__ int doffT[NDIAG + 2];

    for (int k = threadIdx.x; k < NDIAG + 2; k += 128)
        doffT[k] = (k < NDIAG) ? doffs(k) : 0;
    for (int k = lane; k < N; k += 32) sp_s[w][k] = input[prob * N + k];
    float st5[5];
#pragma unroll
    for (int g = 0; g < 5; ++g) st5[g] = target[prob * N + lane + 32 * g];
    __syncthreads();

    const float* spw = sp_s[w];
    const int pb = prob * NCELLS;
    float Rcur[5], uprev[5];
#pragma unroll
    for (int g = 0; g < 5; ++g) { Rcur[g] = BIGV; uprev[g] = BIGV; }

    // ---------------- forward: gated shuffle wavefront ----------------
    for (int s = 0; s < NDIAG; ++s) {
        float u[5];
#pragma unroll
        for (int g = 0; g < 5; ++g)
            if ((unsigned)(s - 32 * g) <= 191u)
                u[g] = __shfl_sync(FULLM, Rcur[g], (lane + 31) & 31);
        const int dof = doffT[s];
        const int rmin = max(0, s - (N - 1));
#pragma unroll
        for (int g = 0; g < 5; ++g) {
            if ((unsigned)(s - 32 * g) > 191u) continue;  // warp-uniform gate
            const int ri = lane + 32 * g;
            const int c = s - ri;
            if ((unsigned)c >= (unsigned)N) continue;  // per-lane predicate
            const bool origin = (g == 0) && (lane == 0);  // ri == 0
            float upv, dg;
            if (g == 0) {
                const float uu = (lane == 0) ? BIGV : u[0];
                upv = uu;  // BIGV when ri==0
                dg = (c == 0) ? (origin ? 0.0f : BIGV)
                              : (origin ? BIGV : uprev[0]);
            } else {
                upv = (lane == 0) ? u[g - 1] : u[g];
                dg = (c == 0) ? BIGV : uprev[g];
            }
            const float lf = (c == 0) ? BIGV : Rcur[g];
            float diff = st5[g] - spw[c];
            const float d = diff * diff;
            const float mn = fminf(dg, fminf(upv, lf));
            const float mnK = mn * KLOG2E;
            const float ea = ex2f(fmaf(dg, NEGK, mnK));
            const float eb = ex2f(fmaf(upv, NEGK, mnK));
            const float ec = ex2f(fmaf(lf, NEGK, mnK));
            const float ssum = ea + eb + ec;
            const float r = fmaf(NGLN2, lg2f(ssum), d + mn);
            const float inv = rcpf(ssum);
            g_w2[pb + dof + (ri - rmin)] = make_float2(ea * inv, eb * inv);
            uprev[g] = upv;
            Rcur[g] = r;
        }
    }
    if (lane == 31) g_sdtw[prob] = Rcur[4];  // R[N-1][N-1]

    __threadfence_block();  // order weight stores before cp.async readback

    // ---------------- backward: gated reverse wavefront, cp.async ring -------
    auto prefetch = [&](int d) {
        const float2* src = g_w2 + pb + doffT[d] + lane;
        uint32_t dst = smem_u32(&ring[w][d & 7][lane]);
#pragma unroll
        for (int k = 0; k < 5; ++k)
            cpa8(dst + (uint32_t)(k * 32 * sizeof(float2)), src + k * 32);
        CP_COMMIT();
    };
#pragma unroll
    for (int d = NDIAG - 1; d >= NDIAG - 6; --d) prefetch(d);  // 318..313

    float Ecur[5], dprev[5], ddf[5];
#pragma unroll
    for (int g = 0; g < 5; ++g) {
        Ecur[g] = 0.0f;
        dprev[g] = 0.0f;
        ddf[g] = (float)(2 * (lane + 32 * g) - (NDIAG - 1));  // = ri - c at sb=318
    }
    float acc = 0.0f;

    for (int sb = NDIAG - 1; sb >= 0; --sb) {
        CP_WAIT6();  // diag sb+1 (and older) staged
        float sd[5];
#pragma unroll
        for (int g = 0; g < 5; ++g)
            if ((unsigned)(sb - (32 * g - 1)) <= 191u)
                sd[g] = __shfl_sync(FULLM, Ecur[g], (lane + 1) & 31);
        const float2* ch1 = ring[w][(sb + 1) & 7];
        const float2* ch2 = ring[w][(sb + 2) & 7];
        const int rm1 = max(0, sb + 1 - (N - 1));
        const int rm2 = max(0, sb + 2 - (N - 1));
#pragma unroll
        for (int g = 0; g < 5; ++g) {
            if ((unsigned)(sb - (32 * g - 1)) > 191u) {
                ddf[g] += 1.0f;
                continue;
            }
            const int ri = lane + 32 * g;
            const int c = sb - ri;
            if ((unsigned)c < (unsigned)N) {
                float ev;
                if (sb == NDIAG - 1) {
                    ev = 1.0f;  // seed E[N-1][N-1]
                } else {
                    const float echild =
                        (lane < 31) ? sd[g] : ((g < 4) ? sd[g + 1] : 0.0f);
                    ev = 0.0f;
                    if (ri + 1 < N) {  // child (ri+1, c): its wu
                        const float2 f = ch1[ri + 1 - rm1];
                        ev += echild * f.y;
                        if (c + 1 < N) {  // child (ri+1, c+1): its wd
                            const float2 h = ch2[ri + 1 - rm2];
                            ev = fmaf(dprev[g], h.x, ev);
                        }
                    }
                    if (c + 1 < N) {  // child (ri, c+1): its wl = 1-wd-wu
                        const float2 q = ch1[ri - rm1];
                        ev = fmaf(Ecur[g], 1.0f - q.x - q.y, ev);
                    }
                    dprev[g] = echild;
                }
                Ecur[g] = ev;
                const float t = ev * ddf[g];
                acc = fmaf(t, ddf[g], acc);
            }
            ddf[g] += 1.0f;
        }
        const int pf = sb - 6;
        if (pf >= 0) prefetch(pf);
    }

    // warp reduction of temporal accumulator
#pragma unroll
    for (int o = 16; o; o >>= 1) acc += __shfl_down_sync(FULLM, acc, o);
    if (lane == 0) g_lt[prob] = acc * (1.0f / (float)NCELLS);
}

__global__ __launch_bounds__(BATCH) void dtw_reduce_kernel(
    float* __restrict__ out) {
    __shared__ float sh[BATCH];
    const int b = threadIdx.x;
    float ls = 0.0f, lt = 0.0f;
#pragma unroll
    for (int c = 0; c < CH; ++c) {
        ls += g_sdtw[b * CH + c];
        lt += g_lt[b * CH + c];
    }
    ls *= (1.0f / (float)CH);
    lt *= (1.0f / (float)CH);
    out[1 + b] = ls;          // loss_shape
    out[1 + BATCH + b] = lt;  // loss_temporal
    sh[b] = 0.5f * ls + 0.5f * lt;
    __syncthreads();
    if (b == 0) {
        float tot = 0.0f;
#pragma unroll
        for (int k = 0; k < BATCH; ++k) tot += sh[k];
        out[0] = tot * (1.0f / (float)BATCH);  // loss
    }
}

extern "C" void kernel_launch(void* const* d_in, const int* in_sizes, int n_in,
                              void* d_out, int out_size) {
    const float* input = (const float*)d_in[0];
    const float* target = (const float*)d_in[1];
    float* out = (float*)d_out;
    dtw_warp_kernel<<<BC / 4, 128>>>(input, target);
    dtw_reduce_kernel<<<1, BATCH>>>(out);
}

// round 12
// speedup vs baseline: 1.0306x; 1.0306x over previous
#include <cuda_runtime.h>
#include <cstdint>

#define N 160
#define NCELLS (N * N)
#define NDIAG (2 * N - 1)  // 319 anti-diagonals, 0-based s = ri + c
#define BC 512
#define CH 8
#define BATCH 64
#define WPB 8               // warps per block (2 per SMSP)
#define BIGV 1e10f
#define GAMMA 0.01f
#define FULLM 0xffffffffu

// exp/log folding constants
#define KLOG2E 144.26950408889634f      // (1/GAMMA) * log2(e)
#define NEGK (-144.26950408889634f)
#define NGLN2 (-0.006931471805599453f)  // -GAMMA * ln(2)

// dynamic smem layout
#define SP_BYTES (WPB * N * 4)                    // 5120
#define RING_BYTES (WPB * 8 * N * 8)              // 81920
#define DOFF_BYTES ((NDIAG + 2) * 4)
#define SMEM_TOTAL (SP_BYTES + RING_BYTES + DOFF_BYTES)

// Softmin gradient weights per cell: (wd, wu) packed; wl = 1 - wd - wu.
// Diag-major compacted. +256 cells padding for fixed-size prefetch overrun.
__device__ float2 g_w2[(size_t)BC * NCELLS + 256];
__device__ float g_sdtw[BC];
__device__ float g_lt[BC];

__device__ __forceinline__ int doffs(int s) {
    return (s <= 160) ? (s * (s + 1)) / 2
                      : NCELLS - ((319 - s) * (320 - s)) / 2;
}

__device__ __forceinline__ float ex2f(float x) {
    float r;
    asm("ex2.approx.f32 %0, %1;" : "=f"(r) : "f"(x));
    return r;
}
__device__ __forceinline__ float lg2f(float x) {
    float r;
    asm("lg2.approx.f32 %0, %1;" : "=f"(r) : "f"(x));
    return r;
}
__device__ __forceinline__ float rcpf(float x) {
    float r;
    asm("rcp.approx.f32 %0, %1;" : "=f"(r) : "f"(x));
    return r;
}
__device__ __forceinline__ uint32_t smem_u32(const void* p) {
    return (uint32_t)__cvta_generic_to_shared(p);
}
__device__ __forceinline__ void cpa8(uint32_t dst, const void* src) {
    asm volatile("cp.async.ca.shared.global [%0], [%1], 8;" ::"r"(dst),
                 "l"(src));
}
#define CP_COMMIT() asm volatile("cp.async.commit_group;" ::: "memory")
#define CP_WAIT6() asm volatile("cp.async.wait_group 6;" ::: "memory")

__global__ __launch_bounds__(32 * WPB) void dtw_warp_kernel(
    const float* __restrict__ input, const float* __restrict__ target) {
    const int lane = threadIdx.x & 31;
    const int w = threadIdx.x >> 5;
    const int prob = blockIdx.x * WPB + w;  // 1 warp = 1 problem

    extern __shared__ char dyn[];
    float* sp_all = (float*)dyn;                       // [WPB][N]
    float2* ring_all = (float2*)(dyn + SP_BYTES);      // [WPB][8][N]
    int* doffT = (int*)(dyn + SP_BYTES + RING_BYTES);  // [NDIAG+2]

    float* spw = sp_all + w * N;
    float2* ringw = ring_all + w * 8 * N;

    for (int k = threadIdx.x; k < NDIAG + 2; k += 32 * WPB)
        doffT[k] = (k < NDIAG) ? doffs(k) : 0;
    for (int k = lane; k < N; k += 32) spw[k] = input[prob * N + k];
    float st5[5];
#pragma unroll
    for (int g = 0; g < 5; ++g) st5[g] = target[prob * N + lane + 32 * g];
    __syncthreads();

    const int pb = prob * NCELLS;
    float Rcur[5], uprev[5];
#pragma unroll
    for (int g = 0; g < 5; ++g) { Rcur[g] = BIGV; uprev[g] = BIGV; }

    // ---------------- forward: shuffle-synchronized wavefront ----------------
    for (int s = 0; s < NDIAG; ++s) {
        float u[5];
#pragma unroll
        for (int g = 0; g < 5; ++g)
            u[g] = __shfl_sync(FULLM, Rcur[g], (lane + 31) & 31);
        const int dof = doffT[s];
        const int rmin = max(0, s - (N - 1));
#pragma unroll
        for (int g = 0; g < 5; ++g) {
            const int ri = lane + 32 * g;
            const int c = s - ri;
            if (c < 0 || c >= N) continue;
            const float uu = (lane == 0) ? ((g == 0) ? BIGV : u[g - 1]) : u[g];
            const float upv = (ri == 0) ? BIGV : uu;
            const float dg = (c == 0) ? ((ri == 0) ? 0.0f : BIGV)
                                      : ((ri == 0) ? BIGV : uprev[g]);
            const float lf = (c == 0) ? BIGV : Rcur[g];
            float diff = st5[g] - spw[c];
            const float d = diff * diff;
            const float mn = fminf(dg, fminf(upv, lf));
            const float mnK = mn * KLOG2E;
            const float ea = ex2f(fmaf(dg, NEGK, mnK));
            const float eb = ex2f(fmaf(upv, NEGK, mnK));
            const float ec = ex2f(fmaf(lf, NEGK, mnK));
            const float ssum = ea + eb + ec;
            const float r = fmaf(NGLN2, lg2f(ssum), d + mn);
            const float inv = rcpf(ssum);
            g_w2[pb + dof + (ri - rmin)] = make_float2(ea * inv, eb * inv);
            uprev[g] = upv;
            Rcur[g] = r;
        }
    }
    if (lane == 31) g_sdtw[prob] = Rcur[4];  // R[N-1][N-1]

    __threadfence_block();  // order weight stores before cp.async readback

    // ---------------- backward: reverse wavefront, cp.async-staged weights ---
    // diag d staged into ring slot d&7; first read at iteration d-1 (as sb+1).
    auto prefetch = [&](int d) {
        const float2* src = g_w2 + pb + doffT[d] + lane;
        uint32_t dst = smem_u32(&ringw[(d & 7) * N + lane]);
#pragma unroll
        for (int k = 0; k < 5; ++k)
            cpa8(dst + (uint32_t)(k * 32 * sizeof(float2)), src + k * 32);
        CP_COMMIT();
    };
#pragma unroll
    for (int d = NDIAG - 1; d >= NDIAG - 6; --d) prefetch(d);  // 318..313

    float Ecur[5], dprev[5];
#pragma unroll
    for (int g = 0; g < 5; ++g) { Ecur[g] = 0.0f; dprev[g] = 0.0f; }
    float acc = 0.0f;

    for (int sb = NDIAG - 1; sb >= 0; --sb) {
        CP_WAIT6();  // guarantees diag sb+1 (and older) staged
        float sd[5];
#pragma unroll
        for (int g = 0; g < 5; ++g)
            sd[g] = __shfl_sync(FULLM, Ecur[g], (lane + 1) & 31);
        const float2* ch1 = ringw + ((sb + 1) & 7) * N;
        const float2* ch2 = ringw + ((sb + 2) & 7) * N;
        const int rm1 = max(0, sb + 1 - (N - 1));
        const int rm2 = max(0, sb + 2 - (N - 1));
#pragma unroll
        for (int g = 0; g < 5; ++g) {
            const int ri = lane + 32 * g;
            const int c = sb - ri;
            if (c < 0 || c >= N) continue;
            float ev;
            if (sb == NDIAG - 1) {
                ev = 1.0f;  // seed E[N-1][N-1]
            } else {
                const float echild =
                    (lane < 31) ? sd[g] : ((g < 4) ? sd[g + 1] : 0.0f);
                ev = 0.0f;
                if (ri + 1 < N) {  // child (ri+1, c): its wu
                    const float2 f = ch1[ri + 1 - rm1];
                    ev += echild * f.y;
                    if (c + 1 < N) {  // child (ri+1, c+1): its wd
                        const float2 h = ch2[ri + 1 - rm2];
                        ev = fmaf(dprev[g], h.x, ev);
                    }
                }
                if (c + 1 < N) {  // child (ri, c+1): its wl = 1-wd-wu
                    const float2 q = ch1[ri - rm1];
                    ev = fmaf(Ecur[g], 1.0f - q.x - q.y, ev);
                }
                dprev[g] = echild;
            }
            Ecur[g] = ev;
            const float dd = (float)(ri - c);
            acc = fmaf(ev * dd, dd, acc);
        }
        const int pf = sb - 6;
        if (pf >= 0) prefetch(pf);
    }

    // warp reduction of temporal accumulator
#pragma unroll
    for (int o = 16; o; o >>= 1) acc += __shfl_down_sync(FULLM, acc, o);
    if (lane == 0) g_lt[prob] = acc * (1.0f / (float)NCELLS);
}

__global__ __launch_bounds__(BATCH) void dtw_reduce_kernel(
    float* __restrict__ out) {
    __shared__ float sh[BATCH];
    const int b = threadIdx.x;
    float ls = 0.0f, lt = 0.0f;
#pragma unroll
    for (int c = 0; c < CH; ++c) {
        ls += g_sdtw[b * CH + c];
        lt += g_lt[b * CH + c];
    }
    ls *= (1.0f / (float)CH);
    lt *= (1.0f / (float)CH);
    out[1 + b] = ls;          // loss_shape
    out[1 + BATCH + b] = lt;  // loss_temporal
    sh[b] = 0.5f * ls + 0.5f * lt;
    __syncthreads();
    if (b == 0) {
        float tot = 0.0f;
#pragma unroll
        for (int k = 0; k < BATCH; ++k) tot += sh[k];
        out[0] = tot * (1.0f / (float)BATCH);  // loss
    }
}

extern "C" void kernel_launch(void* const* d_in, const int* in_sizes, int n_in,
                              void* d_out, int out_size) {
    const float* input = (const float*)d_in[0];
    const float* target = (const float*)d_in[1];
    float* out = (float*)d_out;
    cudaFuncSetAttribute(dtw_warp_kernel,
                         cudaFuncAttributeMaxDynamicSharedMemorySize,
                         SMEM_TOTAL);
    dtw_warp_kernel<<<BC / WPB, 32 * WPB, SMEM_TOTAL>>>(input, target);
    dtw_reduce_kernel<<<1, BATCH>>>(out);
}

// round 13
// speedup vs baseline: 2.1152x; 2.0523x over previous
#include <cuda_runtime.h>
#include <cstdint>

#define N 160
#define NCELLS (N * N)
#define NDIAG (2 * N - 1)  // 319 anti-diagonals, 0-based s = ri + c
#define BC 512
#define CH 8
#define BATCH 64
#define BIGV 1e10f
#define FULLM 0xffffffffu

// exp/log folding constants (gamma = 0.01)
#define KLOG2E 144.26950408889634f      // (1/GAMMA) * log2(e)
#define NEGK (-144.26950408889634f)
#define NGLN2 (-0.006931471805599453f)  // -GAMMA * ln(2)

// Softmin gradient weights per cell: (wd, wu) packed; wl = 1 - wd - wu.
// Diag-major compacted. +256 cells padding for fixed-size prefetch overrun.
__device__ float2 g_w2[(size_t)BC * NCELLS + 256];
__device__ float g_sdtw[BC];
__device__ float g_lt[BC];

__device__ __forceinline__ int doffs(int s) {
    return (s <= 160) ? (s * (s + 1)) / 2
                      : NCELLS - ((319 - s) * (320 - s)) / 2;
}

__device__ __forceinline__ float ex2f(float x) {
    float r;
    asm("ex2.approx.f32 %0, %1;" : "=f"(r) : "f"(x));
    return r;
}
__device__ __forceinline__ float lg2f(float x) {
    float r;
    asm("lg2.approx.f32 %0, %1;" : "=f"(r) : "f"(x));
    return r;
}
__device__ __forceinline__ float rcpf(float x) {
    float r;
    asm("rcp.approx.f32 %0, %1;" : "=f"(r) : "f"(x));
    return r;
}
__device__ __forceinline__ uint32_t smem_u32(const void* p) {
    return (uint32_t)__cvta_generic_to_shared(p);
}
__device__ __forceinline__ void cpa8(uint32_t dst, const void* src) {
    asm volatile("cp.async.ca.shared.global [%0], [%1], 8;" ::"r"(dst),
                 "l"(src));
}
#define CP_COMMIT() asm volatile("cp.async.commit_group;" ::: "memory")
#define CP_WAIT6() asm volatile("cp.async.wait_group 6;" ::: "memory")

// Branch-free predicated store of a float2 (predicated-off -> no mem access).
__device__ __forceinline__ void st_pred2(unsigned act, float2* ptr, float x,
                                         float y) {
    asm volatile(
        "{\n\t.reg .pred p;\n\tsetp.ne.u32 p, %0, 0;\n\t"
        "@p st.global.v2.f32 [%1], {%2, %3};\n\t}"
        ::"r"(act), "l"(ptr), "f"(x), "f"(y)
        : "memory");
}

__global__ __launch_bounds__(128) void dtw_warp_kernel(
    const float* __restrict__ input, const float* __restrict__ target) {
    const int lane = threadIdx.x & 31;
    const int w = threadIdx.x >> 5;
    const int prob = blockIdx.x * 4 + w;  // 1 warp = 1 problem

    __shared__ float sp_s[4][N];
    __shared__ float2 ring[4][8][N];  // per-warp 8-slot diagonal ring
    __shared__ int doffT[NDIAG + 2];

    for (int k = threadIdx.x; k < NDIAG + 2; k += 128)
        doffT[k] = (k < NDIAG) ? doffs(k) : 0;
    for (int k = lane; k < N; k += 32) sp_s[w][k] = input[prob * N + k];
    float st5[5];
#pragma unroll
    for (int g = 0; g < 5; ++g) st5[g] = target[prob * N + lane + 32 * g];
    __syncthreads();

    const float* spw = sp_s[w];
    const int pb = prob * NCELLS;
    float Rcur[5], uprev[5];
#pragma unroll
    for (int g = 0; g < 5; ++g) { Rcur[g] = BIGV; uprev[g] = BIGV; }

    // ---------------- forward: branch-free shuffle wavefront ----------------
    // Inactive lanes compute harmless garbage; only the STG is predicated.
    for (int s = 0; s < NDIAG; ++s) {
        float u[5];
#pragma unroll
        for (int g = 0; g < 5; ++g)
            u[g] = __shfl_sync(FULLM, Rcur[g], (lane + 31) & 31);
        const int dof = doffT[s];
        const int rmin = max(0, s - (N - 1));
        float2* const diagbase = g_w2 + (pb + dof - rmin);
#pragma unroll
        for (int g = 0; g < 5; ++g) {
            const int ri = lane + 32 * g;
            const int c = s - ri;
            const unsigned act = (unsigned)c < (unsigned)N;
            const int cc = min(max(c, 0), N - 1);
            float upv, dg;
            if (g == 0) {
                const bool l0 = (lane == 0);
                upv = l0 ? BIGV : u[0];
                dg = (c == 0) ? (l0 ? 0.0f : BIGV) : (l0 ? BIGV : uprev[0]);
            } else {
                upv = (lane == 0) ? u[g - 1] : u[g];
                dg = (c == 0) ? BIGV : uprev[g];
            }
            const float lf = (c == 0) ? BIGV : Rcur[g];
            const float diff = st5[g] - spw[cc];
            const float d = diff * diff;
            const float mn = fminf(dg, fminf(upv, lf));
            const float mnK = mn * KLOG2E;
            const float ea = ex2f(fmaf(dg, NEGK, mnK));
            const float eb = ex2f(fmaf(upv, NEGK, mnK));
            const float ec = ex2f(fmaf(lf, NEGK, mnK));
            const float ssum = ea + eb + ec;
            const float r = fmaf(NGLN2, lg2f(ssum), d + mn);
            const float inv = rcpf(ssum);
            st_pred2(act, diagbase + ri, ea * inv, eb * inv);
            uprev[g] = upv;
            Rcur[g] = r;
        }
    }
    if (lane == 31) g_sdtw[prob] = Rcur[4];  // R[N-1][N-1]

    __threadfence_block();  // order weight stores before cp.async readback

    // ---------------- backward: branch-free reverse wavefront ----------------
    float2* const ringw = &ring[w][0][0];
    auto prefetch = [&](int d) {
        const float2* src = g_w2 + pb + doffT[d] + lane;
        uint32_t dst = smem_u32(ringw + (d & 7) * N + lane);
#pragma unroll
        for (int k = 0; k < 5; ++k)
            cpa8(dst + (uint32_t)(k * 32 * sizeof(float2)), src + k * 32);
        CP_COMMIT();
    };
#pragma unroll
    for (int d = NDIAG - 1; d >= NDIAG - 7; --d) prefetch(d);  // 318..312

    float Ecur[5], dprev[5];
#pragma unroll
    for (int g = 0; g < 5; ++g) { Ecur[g] = 0.0f; dprev[g] = 0.0f; }
    Ecur[4] = (lane == 31) ? 1.0f : 0.0f;  // seed E[N-1][N-1] (sb = 318)
    float acc = 0.0f;                       // seed contributes 0 (ri == c)

    for (int sb = NDIAG - 2; sb >= 0; --sb) {
        CP_WAIT6();  // diag sb+1 (and older) staged
        float sd[5];
#pragma unroll
        for (int g = 0; g < 5; ++g)
            sd[g] = __shfl_sync(FULLM, Ecur[g], (lane + 1) & 31);
        const float2* ch1 = ringw + ((sb + 1) & 7) * N;
        const float2* ch2 = ringw + ((sb + 2) & 7) * N;
        const int rm1 = max(0, sb + 1 - (N - 1));
        const int rm2 = max(0, sb + 2 - (N - 1));
#pragma unroll
        for (int g = 0; g < 5; ++g) {
            const int ri = lane + 32 * g;
            const int c = sb - ri;
            const unsigned act = (unsigned)c < (unsigned)N;
            const float echild =
                (lane < 31) ? sd[g] : ((g < 4) ? sd[g + 1] : 0.0f);
            const int i1 = min(max(ri + 1 - rm1, 0), N - 1);
            const int i0 = min(max(ri - rm1, 0), N - 1);
            const int i2 = min(max(ri + 1 - rm2, 0), N - 1);
            const float2 f = ch1[i1];  // child (ri+1, c):   wu
            const float2 q = ch1[i0];  // child (ri, c+1):   wl = 1-wd-wu
            const float2 h = ch2[i2];  // child (ri+1, c+1): wd
            const bool rok = (ri + 1 < N);
            const bool cok = (c + 1 < N);
            const float wuv = rok ? f.y : 0.0f;
            const float wlv = cok ? (1.0f - q.x - q.y) : 0.0f;
            const float wdv = (rok && cok) ? h.x : 0.0f;
            float ev = echild * wuv;
            ev = fmaf(dprev[g], wdv, ev);
            ev = fmaf(Ecur[g], wlv, ev);
            dprev[g] = echild;
            Ecur[g] = ev;
            const float dd = (float)(ri - c);
            const float evm = act ? ev : 0.0f;
            acc = fmaf(evm * dd, dd, acc);
        }
        prefetch(max(sb - 6, 0));  // clamped: redundant re-fetch near sb=0 is harmless
    }

    // warp reduction of temporal accumulator
#pragma unroll
    for (int o = 16; o; o >>= 1) acc += __shfl_down_sync(FULLM, acc, o);
    if (lane == 0) g_lt[prob] = acc * (1.0f / (float)NCELLS);
}

__global__ __launch_bounds__(BATCH) void dtw_reduce_kernel(
    float* __restrict__ out) {
    __shared__ float sh[BATCH];
    const int b = threadIdx.x;
    float ls = 0.0f, lt = 0.0f;
#pragma unroll
    for (int c = 0; c < CH; ++c) {
        ls += g_sdtw[b * CH + c];
        lt += g_lt[b * CH + c];
    }
    ls *= (1.0f / (float)CH);
    lt *= (1.0f / (float)CH);
    out[1 + b] = ls;          // loss_shape
    out[1 + BATCH + b] = lt;  // loss_temporal
    sh[b] = 0.5f * ls + 0.5f * lt;
    __syncthreads();
    if (b == 0) {
        float tot = 0.0f;
#pragma unroll
        for (int k = 0; k < BATCH; ++k) tot += sh[k];
        out[0] = tot * (1.0f / (float)BATCH);  // loss
    }
}

extern "C" void kernel_launch(void* const* d_in, const int* in_sizes, int n_in,
                              void* d_out, int out_size) {
    const float* input = (const float*)d_in[0];
    const float* target = (const float*)d_in[1];
    float* out = (float*)d_out;
    dtw_warp_kernel<<<BC / 4, 128>>>(input, target);
    dtw_reduce_kernel<<<1, BATCH>>>(out);
}